// round 13
// baseline (speedup 1.0000x reference)
#include <cuda_runtime.h>
#include <cuda_fp16.h>
#include <cstdint>

#define WSZ 64
#define DIM 64
#define QBLK 128   // two 64-query blocks per CTA
#define WROWS 192  // KV window rows: [q0-64, q0+128)
#define KVSTR 72   // K/V row stride in halves -> conflict-free ldmatrix / fill stores
#define QSCALE 0.18033688011112042f   // (1/8) * log2(e); softmax in exp2 domain

// SMEM: sM float[192->256] (1024B) + sK half[192*72] + sV half[192*72] = 56320 B -> 4 CTAs/SM
// Two sequential passes (p=0,1) over the same KV window, pass row offset 64p.
// Column permutations (R10): K k-dim / V n-dim permuted at fill so Q fragments
// and O epilogue are single float4 accesses. Dot products invariant.

__device__ __forceinline__ uint32_t pack2h(float x, float y) {
    __half2 h = __floats2half2_rn(x, y);
    return *reinterpret_cast<uint32_t*>(&h);
}

__device__ __forceinline__ void mma_f16(float c[4],
    uint32_t a0, uint32_t a1, uint32_t a2, uint32_t a3, uint32_t b0, uint32_t b1)
{
    asm volatile("mma.sync.aligned.m16n8k16.row.col.f32.f16.f16.f32 "
        "{%0,%1,%2,%3}, {%4,%5,%6,%7}, {%8,%9}, {%0,%1,%2,%3};"
        : "+f"(c[0]), "+f"(c[1]), "+f"(c[2]), "+f"(c[3])
        : "r"(a0), "r"(a1), "r"(a2), "r"(a3), "r"(b0), "r"(b1));
}

__device__ __forceinline__ void ldsm_x4(uint32_t& r0, uint32_t& r1, uint32_t& r2, uint32_t& r3, uint32_t addr) {
    asm volatile("ldmatrix.sync.aligned.m8n8.x4.shared.b16 {%0,%1,%2,%3}, [%4];"
        : "=r"(r0), "=r"(r1), "=r"(r2), "=r"(r3) : "r"(addr));
}
__device__ __forceinline__ void ldsm_x4_t(uint32_t& r0, uint32_t& r1, uint32_t& r2, uint32_t& r3, uint32_t addr) {
    asm volatile("ldmatrix.sync.aligned.m8n8.x4.trans.shared.b16 {%0,%1,%2,%3}, [%4];"
        : "=r"(r0), "=r"(r1), "=r"(r2), "=r"(r3) : "r"(addr));
}

__global__ __launch_bounds__(128, 4)
void lca_kernel(const float* __restrict__ q, const float* __restrict__ k,
                const float* __restrict__ v, const int* __restrict__ mask,
                float* __restrict__ out, int T, int H)
{
    extern __shared__ char smraw[];
    float*  sM = (float*)smraw;                       // 192 floats (pad to 256)
    __half* sK = (__half*)(smraw + 1024);             // 192 x 72
    __half* sV = sK + WROWS * KVSTR;                  // 192 x 72

    const int j   = blockIdx.x;          // pair of query blocks
    const int h   = blockIdx.y;
    const int b   = blockIdx.z;
    const int tid = threadIdx.x;         // 128 threads
    const int wp  = tid >> 5;
    const int ln  = tid & 31;
    const int g   = ln >> 2;             // 0..7
    const int t   = ln & 3;              // 0..3

    const long rowstride = (long)H * DIM;
    const long bbase     = (long)b * T * rowstride;
    const int  q0        = j * QBLK;

    // ---- mask window: rows [q0-64, q0+128)
    for (int i = tid; i < WROWS; i += 128) {
        int kg = q0 + i - WSZ;
        sM[i] = (kg >= 0) ? (float)mask[(long)b * T + kg] : 0.0f;
    }

    // ---- K, V fill (192 rows) as fp16 with column permutation
    #pragma unroll
    for (int it = 0; it < 24; ++it) {
        int idx = tid + it * 128;            // 192 rows * 16 float4
        int r   = idx >> 4;
        int c   = idx & 15;                  // source float4: actual cols 4c..4c+3
        int kg  = q0 + r - WSZ;
        float4 kv = make_float4(0.f, 0.f, 0.f, 0.f);
        float4 vv = make_float4(0.f, 0.f, 0.f, 0.f);
        if (kg >= 0) {
            long off = bbase + (long)kg * rowstride + h * DIM + c * 4;
            kv = *(const float4*)(k + off);
            vv = *(const float4*)(v + off);
        }
        const int pbase = r * KVSTR + ((c >> 2) << 4) + ((c & 3) << 1);
        *(uint32_t*)(sK + pbase)     = pack2h(kv.x, kv.y);
        *(uint32_t*)(sK + pbase + 8) = pack2h(kv.z, kv.w);
        *(uint32_t*)(sV + pbase)     = pack2h(vv.x, vv.y);
        *(uint32_t*)(sV + pbase + 8) = pack2h(vv.z, vv.w);
    }

    __syncthreads();   // single sync; both passes read-only after this

    const uint32_t sK_u = (uint32_t)__cvta_generic_to_shared(sK);
    const uint32_t sV_u = (uint32_t)__cvta_generic_to_shared(sV);

    const int r8   = ln & 7;
    const int hi8  = (ln >> 3) & 1;
    const int hi16 = ln >> 4;

    // ---- band masks: diff = 8x + 2t + u - g (pass-invariant)
    unsigned bnda = 0, bndb = 0;
    #pragma unroll
    for (int x = 0; x < 10; ++x) {
        #pragma unroll
        for (int u = 0; u < 2; ++u) {
            const int d = 8 * x + 2 * t + u - g;
            if (d >= 1 && d <= WSZ)          bnda |= 1u << (2 * x + u);
            if (d >= 9 && d <= WSZ + 8)      bndb |= 1u << (2 * x + u);
        }
    }

    const int ia = wp * 16 + g;          // local query row within pass
    const int ib = ia + 8;

    #pragma unroll 1
    for (int p = 0; p < 2; ++p) {
        const int roff = p * WSZ;                    // pass row offset in window
        const int qrow = q0 + roff;                  // first query of this pass

        // ---- Q A-fragments: ONE float4 per (row, ks) thanks to K permutation
        const float* qra = q + bbase + (long)(qrow + ia) * rowstride + h * DIM;
        const float* qrb = qra + 8 * rowstride;
        uint32_t aQ[4][4];
        #pragma unroll
        for (int ks = 0; ks < 4; ++ks) {
            float4 qa = __ldcs((const float4*)(qra + ks * 16 + 4 * t));
            float4 qb = __ldcs((const float4*)(qrb + ks * 16 + 4 * t));
            aQ[ks][0] = pack2h(qa.x * QSCALE, qa.y * QSCALE);
            aQ[ks][2] = pack2h(qa.z * QSCALE, qa.w * QSCALE);
            aQ[ks][1] = pack2h(qb.x * QSCALE, qb.y * QSCALE);
            aQ[ks][3] = pack2h(qb.z * QSCALE, qb.w * QSCALE);
        }

        // ---- QK^T: band tiles x = 0..9 within this pass's 128-row key window
        float S[10][4];
        #pragma unroll
        for (int x = 0; x < 10; ++x)
            S[x][0] = S[x][1] = S[x][2] = S[x][3] = 0.f;

        #pragma unroll
        for (int e = 0; e < 5; ++e) {
            const int key  = roff + (2 * wp + 2 * e) * 8 + (hi16 << 3) + r8;
            const uint32_t rowaddr = sK_u + (uint32_t)(key * KVSTR) * 2;
            #pragma unroll
            for (int ks = 0; ks < 4; ++ks) {
                const int hoff = ks * 16 + (hi8 << 3);
                uint32_t b0, b1, b2, b3;
                ldsm_x4(b0, b1, b2, b3, rowaddr + (uint32_t)hoff * 2);
                mma_f16(S[2 * e],     aQ[ks][0], aQ[ks][1], aQ[ks][2], aQ[ks][3], b0, b1);
                mma_f16(S[2 * e + 1], aQ[ks][0], aQ[ks][1], aQ[ks][2], aQ[ks][3], b2, b3);
            }
        }

        // ---- unsafe softmax in exp2 domain; validity applied as multiply
        uint32_t P[10][2];
        float sa = 0.f, sb = 0.f;
        #pragma unroll
        for (int x = 0; x < 10; ++x) {
            const int mbase = roff + (2 * wp + x) * 8 + 2 * t;
            const float2 mm = *(const float2*)(sM + mbase);
            const float va0 = ((bnda >> (2 * x))     & 1u) ? mm.x : 0.f;
            const float va1 = ((bnda >> (2 * x + 1)) & 1u) ? mm.y : 0.f;
            const float vb0 = ((bndb >> (2 * x))     & 1u) ? mm.x : 0.f;
            const float vb1 = ((bndb >> (2 * x + 1)) & 1u) ? mm.y : 0.f;
            const float pa0 = exp2f(S[x][0]) * va0;
            const float pa1 = exp2f(S[x][1]) * va1;
            const float pb0 = exp2f(S[x][2]) * vb0;
            const float pb1 = exp2f(S[x][3]) * vb1;
            sa += pa0 + pa1;
            sb += pb0 + pb1;
            P[x][0] = pack2h(pa0, pa1);
            P[x][1] = pack2h(pb0, pb1);
        }
        sa += __shfl_xor_sync(0xffffffffu, sa, 1);
        sa += __shfl_xor_sync(0xffffffffu, sa, 2);
        sb += __shfl_xor_sync(0xffffffffu, sb, 1);
        sb += __shfl_xor_sync(0xffffffffu, sb, 2);
        const float inva = (sa > 0.f) ? (1.f / sa) : 0.f;
        const float invb = (sb > 0.f) ? (1.f / sb) : 0.f;
        const __half2 h2a = __floats2half2_rn(inva, inva);
        const __half2 h2b = __floats2half2_rn(invb, invb);

        // ---- P @ V
        float O[8][4];
        #pragma unroll
        for (int nv = 0; nv < 8; ++nv)
            O[nv][0] = O[nv][1] = O[nv][2] = O[nv][3] = 0.f;

        #pragma unroll
        for (int s = 0; s < 5; ++s) {
            __half2 q0h = __hmul2(*(__half2*)&P[2 * s][0],     h2a);
            __half2 q1h = __hmul2(*(__half2*)&P[2 * s][1],     h2b);
            __half2 q2h = __hmul2(*(__half2*)&P[2 * s + 1][0], h2a);
            __half2 q3h = __hmul2(*(__half2*)&P[2 * s + 1][1], h2b);
            const uint32_t pa0 = *(uint32_t*)&q0h;
            const uint32_t pa1 = *(uint32_t*)&q1h;
            const uint32_t pa2 = *(uint32_t*)&q2h;
            const uint32_t pa3 = *(uint32_t*)&q3h;

            const int key = roff + (2 * wp + 2 * s) * 8 + (hi8 << 3) + r8;
            const uint32_t rowaddr = sV_u + (uint32_t)(key * KVSTR) * 2;
            #pragma unroll
            for (int nd = 0; nd < 4; ++nd) {
                const int hoff = nd * 16 + (hi16 << 3);
                uint32_t b0, b1, b2, b3;
                ldsm_x4_t(b0, b1, b2, b3, rowaddr + (uint32_t)hoff * 2);
                mma_f16(O[2 * nd],     pa0, pa1, pa2, pa3, b0, b1);
                mma_f16(O[2 * nd + 1], pa0, pa1, pa2, pa3, b2, b3);
            }
        }

        // ---- epilogue: query-mask, float4 stores thanks to V permutation
        const float qma = sM[roff + WSZ + ia];
        const float qmb = sM[roff + WSZ + ib];
        const long oa = bbase + (long)(qrow + ia) * rowstride + h * DIM;
        const long ob = bbase + (long)(qrow + ib) * rowstride + h * DIM;
        #pragma unroll
        for (int m = 0; m < 4; ++m) {
            const int col = 16 * m + 4 * t;
            __stcs((float4*)(out + oa + col),
                   make_float4(O[2 * m][0] * qma, O[2 * m][1] * qma,
                               O[2 * m + 1][0] * qma, O[2 * m + 1][1] * qma));
            __stcs((float4*)(out + ob + col),
                   make_float4(O[2 * m][2] * qmb, O[2 * m][3] * qmb,
                               O[2 * m + 1][2] * qmb, O[2 * m + 1][3] * qmb));
        }
    }
}

extern "C" void kernel_launch(void* const* d_in, const int* in_sizes, int n_in,
                              void* d_out, int out_size)
{
    const float* q    = (const float*)d_in[0];
    const float* k    = (const float*)d_in[1];
    const float* v    = (const float*)d_in[2];
    const int*   mask = (const int*)d_in[3];

    const int BT = in_sizes[3];            // b*t
    const int H  = in_sizes[0] / BT / DIM; // heads
    const int B  = 4;
    const int T  = BT / B;

    const int smem_bytes = 1024 + 2 * WROWS * KVSTR * (int)sizeof(__half);
    cudaFuncSetAttribute(lca_kernel, cudaFuncAttributeMaxDynamicSharedMemorySize, smem_bytes);

    dim3 grid(T / QBLK, H, B);
    lca_kernel<<<grid, 128, smem_bytes>>>(q, k, v, mask, (float*)d_out, T, H);
}

// round 14
// speedup vs baseline: 1.2993x; 1.2993x over previous
#include <cuda_runtime.h>
#include <cuda_fp16.h>
#include <cstdint>

#define WSZ 64
#define DIM 64
#define KVSTR 72   // K/V row stride in halves -> conflict-free ldmatrix / fill stores
#define QSCALE 0.18033688011112042f   // (1/8) * log2(e); softmax in exp2 domain

// SMEM: sM float[128] (512B) + sK half[128*72] + sV half[128*72] = 37376 B -> 5 CTAs/SM
// Column permutations (R10): K k-dim / V n-dim permuted at fill so Q fragments and
// O epilogue are single float4 accesses. Dot products order-invariant.
// R14: Q LDGs hoisted ahead of KV fill (latency overlap); band masks computed
// before the barrier; softmax sums use split accumulators.

__device__ __forceinline__ uint32_t pack2h(float x, float y) {
    __half2 h = __floats2half2_rn(x, y);
    return *reinterpret_cast<uint32_t*>(&h);
}

__device__ __forceinline__ void mma_f16(float c[4],
    uint32_t a0, uint32_t a1, uint32_t a2, uint32_t a3, uint32_t b0, uint32_t b1)
{
    asm volatile("mma.sync.aligned.m16n8k16.row.col.f32.f16.f16.f32 "
        "{%0,%1,%2,%3}, {%4,%5,%6,%7}, {%8,%9}, {%0,%1,%2,%3};"
        : "+f"(c[0]), "+f"(c[1]), "+f"(c[2]), "+f"(c[3])
        : "r"(a0), "r"(a1), "r"(a2), "r"(a3), "r"(b0), "r"(b1));
}

__device__ __forceinline__ void ldsm_x4(uint32_t& r0, uint32_t& r1, uint32_t& r2, uint32_t& r3, uint32_t addr) {
    asm volatile("ldmatrix.sync.aligned.m8n8.x4.shared.b16 {%0,%1,%2,%3}, [%4];"
        : "=r"(r0), "=r"(r1), "=r"(r2), "=r"(r3) : "r"(addr));
}
__device__ __forceinline__ void ldsm_x4_t(uint32_t& r0, uint32_t& r1, uint32_t& r2, uint32_t& r3, uint32_t addr) {
    asm volatile("ldmatrix.sync.aligned.m8n8.x4.trans.shared.b16 {%0,%1,%2,%3}, [%4];"
        : "=r"(r0), "=r"(r1), "=r"(r2), "=r"(r3) : "r"(addr));
}

__global__ __launch_bounds__(128, 5)
void lca_kernel(const float* __restrict__ q, const float* __restrict__ k,
                const float* __restrict__ v, const int* __restrict__ mask,
                float* __restrict__ out, int T, int H)
{
    extern __shared__ char smraw[];
    float*  sM = (float*)smraw;                       // 128 floats
    __half* sK = (__half*)(smraw + 512);              // 128 x 72
    __half* sV = sK + 128 * KVSTR;                    // 128 x 72

    const int j   = blockIdx.x;
    const int h   = blockIdx.y;
    const int b   = blockIdx.z;
    const int tid = threadIdx.x;          // 128 threads
    const int wp  = tid >> 5;
    const int ln  = tid & 31;
    const int g   = ln >> 2;              // 0..7
    const int t   = ln & 3;               // 0..3

    const long rowstride = (long)H * DIM;
    const long bbase     = (long)b * T * rowstride;
    const int  q0        = j * WSZ;

    // ---- Q loads FIRST (independent; latency overlaps the KV fill below)
    const int ia = wp * 16 + g;
    const int ib = ia + 8;
    const float* qra = q + bbase + (long)(q0 + ia) * rowstride + h * DIM;
    const float* qrb = qra + 8 * rowstride;
    float4 qfa[4], qfb[4];
    #pragma unroll
    for (int ks = 0; ks < 4; ++ks) {
        qfa[ks] = __ldcs((const float4*)(qra + ks * 16 + 4 * t));
        qfb[ks] = __ldcs((const float4*)(qrb + ks * 16 + 4 * t));
    }

    // ---- mask window
    {
        int kg = q0 + tid - WSZ;
        sM[tid] = (kg >= 0) ? (float)mask[(long)b * T + kg] : 0.0f;
    }

    // ---- K, V fill as fp16 with column permutation (zero left pad at j==0)
    #pragma unroll
    for (int it = 0; it < 16; ++it) {
        int idx = tid + it * 128;            // 128 rows * 16 float4
        int r   = idx >> 4;
        int c   = idx & 15;                  // source float4: actual cols 4c..4c+3
        int kg  = q0 + r - WSZ;
        float4 kv = make_float4(0.f, 0.f, 0.f, 0.f);
        float4 vv = make_float4(0.f, 0.f, 0.f, 0.f);
        if (kg >= 0) {
            long off = bbase + (long)kg * rowstride + h * DIM + c * 4;
            kv = *(const float4*)(k + off);
            vv = *(const float4*)(v + off);
        }
        const int pbase = r * KVSTR + ((c >> 2) << 4) + ((c & 3) << 1);
        *(uint32_t*)(sK + pbase)     = pack2h(kv.x, kv.y);
        *(uint32_t*)(sK + pbase + 8) = pack2h(kv.z, kv.w);
        *(uint32_t*)(sV + pbase)     = pack2h(vv.x, vv.y);
        *(uint32_t*)(sV + pbase + 8) = pack2h(vv.z, vv.w);
    }

    // ---- band masks (ALU-only; fills barrier wait): diff = 8x + 2t + u - g
    unsigned bnda = 0, bndb = 0;
    #pragma unroll
    for (int x = 0; x < 10; ++x) {
        #pragma unroll
        for (int u = 0; u < 2; ++u) {
            const int d = 8 * x + 2 * t + u - g;
            if (d >= 1 && d <= WSZ)          bnda |= 1u << (2 * x + u);
            if (d >= 9 && d <= WSZ + 8)      bndb |= 1u << (2 * x + u);
        }
    }

    // ---- pack Q fragments (K-permutation makes them contiguous)
    uint32_t aQ[4][4];
    #pragma unroll
    for (int ks = 0; ks < 4; ++ks) {
        aQ[ks][0] = pack2h(qfa[ks].x * QSCALE, qfa[ks].y * QSCALE);
        aQ[ks][2] = pack2h(qfa[ks].z * QSCALE, qfa[ks].w * QSCALE);
        aQ[ks][1] = pack2h(qfb[ks].x * QSCALE, qfb[ks].y * QSCALE);
        aQ[ks][3] = pack2h(qfb[ks].z * QSCALE, qfb[ks].w * QSCALE);
    }

    __syncthreads();

    const uint32_t sK_u = (uint32_t)__cvta_generic_to_shared(sK);
    const uint32_t sV_u = (uint32_t)__cvta_generic_to_shared(sV);

    const int r8   = ln & 7;
    const int hi8  = (ln >> 3) & 1;
    const int hi16 = ln >> 4;

    // ---- QK^T: band tiles x = 0..9; x4 ldmatrix covers n-tiles {2e, 2e+1}
    float S[10][4];
    #pragma unroll
    for (int x = 0; x < 10; ++x)
        S[x][0] = S[x][1] = S[x][2] = S[x][3] = 0.f;

    #pragma unroll
    for (int e = 0; e < 5; ++e) {
        const int key  = (2 * wp + 2 * e) * 8 + (hi16 << 3) + r8;
        const uint32_t rowaddr = sK_u + (uint32_t)(key * KVSTR) * 2;
        #pragma unroll
        for (int ks = 0; ks < 4; ++ks) {
            const int hoff = ks * 16 + (hi8 << 3);
            uint32_t b0, b1, b2, b3;
            ldsm_x4(b0, b1, b2, b3, rowaddr + (uint32_t)hoff * 2);
            mma_f16(S[2 * e],     aQ[ks][0], aQ[ks][1], aQ[ks][2], aQ[ks][3], b0, b1);
            mma_f16(S[2 * e + 1], aQ[ks][0], aQ[ks][1], aQ[ks][2], aQ[ks][3], b2, b3);
        }
    }

    // ---- unsafe softmax in exp2 domain; validity as multiply; split sums
    uint32_t P[10][2];
    float sa0 = 0.f, sa1 = 0.f, sb0 = 0.f, sb1 = 0.f;
    #pragma unroll
    for (int x = 0; x < 10; ++x) {
        const int mbase = (2 * wp + x) * 8 + 2 * t;
        const float2 mm = *(const float2*)(sM + mbase);
        const float va0 = ((bnda >> (2 * x))     & 1u) ? mm.x : 0.f;
        const float va1 = ((bnda >> (2 * x + 1)) & 1u) ? mm.y : 0.f;
        const float vb0 = ((bndb >> (2 * x))     & 1u) ? mm.x : 0.f;
        const float vb1 = ((bndb >> (2 * x + 1)) & 1u) ? mm.y : 0.f;
        const float pa0 = exp2f(S[x][0]) * va0;
        const float pa1 = exp2f(S[x][1]) * va1;
        const float pb0 = exp2f(S[x][2]) * vb0;
        const float pb1 = exp2f(S[x][3]) * vb1;
        sa0 += pa0;  sa1 += pa1;
        sb0 += pb0;  sb1 += pb1;
        P[x][0] = pack2h(pa0, pa1);
        P[x][1] = pack2h(pb0, pb1);
    }
    float sa = sa0 + sa1;
    float sb = sb0 + sb1;
    sa += __shfl_xor_sync(0xffffffffu, sa, 1);
    sa += __shfl_xor_sync(0xffffffffu, sa, 2);
    sb += __shfl_xor_sync(0xffffffffu, sb, 1);
    sb += __shfl_xor_sync(0xffffffffu, sb, 2);
    const float inva = (sa > 0.f) ? (1.f / sa) : 0.f;
    const float invb = (sb > 0.f) ? (1.f / sb) : 0.f;
    const __half2 h2a = __floats2half2_rn(inva, inva);
    const __half2 h2b = __floats2half2_rn(invb, invb);

    // ---- P @ V (keys dimension unpermuted; V n-positions carry permuted dims)
    float O[8][4];
    #pragma unroll
    for (int nv = 0; nv < 8; ++nv)
        O[nv][0] = O[nv][1] = O[nv][2] = O[nv][3] = 0.f;

    #pragma unroll
    for (int s = 0; s < 5; ++s) {
        __half2 q0h = __hmul2(*(__half2*)&P[2 * s][0],     h2a);
        __half2 q1h = __hmul2(*(__half2*)&P[2 * s][1],     h2b);
        __half2 q2h = __hmul2(*(__half2*)&P[2 * s + 1][0], h2a);
        __half2 q3h = __hmul2(*(__half2*)&P[2 * s + 1][1], h2b);
        const uint32_t pa0 = *(uint32_t*)&q0h;
        const uint32_t pa1 = *(uint32_t*)&q1h;
        const uint32_t pa2 = *(uint32_t*)&q2h;
        const uint32_t pa3 = *(uint32_t*)&q3h;

        const int key = (2 * wp + 2 * s) * 8 + (hi8 << 3) + r8;
        const uint32_t rowaddr = sV_u + (uint32_t)(key * KVSTR) * 2;
        #pragma unroll
        for (int nd = 0; nd < 4; ++nd) {
            const int hoff = nd * 16 + (hi16 << 3);
            uint32_t b0, b1, b2, b3;
            ldsm_x4_t(b0, b1, b2, b3, rowaddr + (uint32_t)hoff * 2);
            mma_f16(O[2 * nd],     pa0, pa1, pa2, pa3, b0, b1);
            mma_f16(O[2 * nd + 1], pa0, pa1, pa2, pa3, b2, b3);
        }
    }

    // ---- epilogue: query-mask, float4 stores thanks to V permutation
    const float qma = sM[WSZ + ia];
    const float qmb = sM[WSZ + ib];
    const long oa = bbase + (long)(q0 + ia) * rowstride + h * DIM;
    const long ob = bbase + (long)(q0 + ib) * rowstride + h * DIM;
    #pragma unroll
    for (int m = 0; m < 4; ++m) {
        const int col = 16 * m + 4 * t;
        __stcs((float4*)(out + oa + col),
               make_float4(O[2 * m][0] * qma, O[2 * m][1] * qma,
                           O[2 * m + 1][0] * qma, O[2 * m + 1][1] * qma));
        __stcs((float4*)(out + ob + col),
               make_float4(O[2 * m][2] * qmb, O[2 * m][3] * qmb,
                           O[2 * m + 1][2] * qmb, O[2 * m + 1][3] * qmb));
    }
}

extern "C" void kernel_launch(void* const* d_in, const int* in_sizes, int n_in,
                              void* d_out, int out_size)
{
    const float* q    = (const float*)d_in[0];
    const float* k    = (const float*)d_in[1];
    const float* v    = (const float*)d_in[2];
    const int*   mask = (const int*)d_in[3];

    const int BT = in_sizes[3];            // b*t
    const int H  = in_sizes[0] / BT / DIM; // heads
    const int B  = 4;
    const int T  = BT / B;

    const int smem_bytes = 512 + 2 * 128 * KVSTR * (int)sizeof(__half);
    cudaFuncSetAttribute(lca_kernel, cudaFuncAttributeMaxDynamicSharedMemorySize, smem_bytes);

    dim3 grid(T / WSZ, H, B);
    lca_kernel<<<grid, 128, smem_bytes>>>(q, k, v, mask, (float*)d_out, T, H);
}

// round 15
// speedup vs baseline: 1.3514x; 1.0401x over previous
#include <cuda_runtime.h>
#include <cuda_fp16.h>
#include <cstdint>

#define WSZ 64
#define DIM 64
#define QBLK 128   // two 64-query blocks per CTA, one per 4-warp group
#define WROWS 192  // KV window rows: [q0-64, q0+128)
#define KVSTR 72   // K/V row stride in halves -> conflict-free ldmatrix / fill stores
#define QSCALE 0.18033688011112042f   // (1/8) * log2(e); softmax in exp2 domain

// SMEM: sM float[192->256] (1024B) + sK half[192*72] + sV half[192*72] = 56320 B
// 256 threads: warp-group 0 (warps 0-3) = queries [q0, q0+64), window rows [0,128)
//              warp-group 1 (warps 4-7) = queries [q0+64, q0+128), rows [64,192)
// Per-warp code identical to the proven 96-reg R10/R14 kernel (wp -> wp&3, +roff).
// Column permutations (R10): K k-dim / V n-dim permuted at fill so Q fragments and
// O epilogue are single float4 accesses. Dot products order-invariant.

__device__ __forceinline__ uint32_t pack2h(float x, float y) {
    __half2 h = __floats2half2_rn(x, y);
    return *reinterpret_cast<uint32_t*>(&h);
}

__device__ __forceinline__ void mma_f16(float c[4],
    uint32_t a0, uint32_t a1, uint32_t a2, uint32_t a3, uint32_t b0, uint32_t b1)
{
    asm volatile("mma.sync.aligned.m16n8k16.row.col.f32.f16.f16.f32 "
        "{%0,%1,%2,%3}, {%4,%5,%6,%7}, {%8,%9}, {%0,%1,%2,%3};"
        : "+f"(c[0]), "+f"(c[1]), "+f"(c[2]), "+f"(c[3])
        : "r"(a0), "r"(a1), "r"(a2), "r"(a3), "r"(b0), "r"(b1));
}

__device__ __forceinline__ void ldsm_x4(uint32_t& r0, uint32_t& r1, uint32_t& r2, uint32_t& r3, uint32_t addr) {
    asm volatile("ldmatrix.sync.aligned.m8n8.x4.shared.b16 {%0,%1,%2,%3}, [%4];"
        : "=r"(r0), "=r"(r1), "=r"(r2), "=r"(r3) : "r"(addr));
}
__device__ __forceinline__ void ldsm_x4_t(uint32_t& r0, uint32_t& r1, uint32_t& r2, uint32_t& r3, uint32_t addr) {
    asm volatile("ldmatrix.sync.aligned.m8n8.x4.trans.shared.b16 {%0,%1,%2,%3}, [%4];"
        : "=r"(r0), "=r"(r1), "=r"(r2), "=r"(r3) : "r"(addr));
}

__global__ __launch_bounds__(256, 2)
void lca_kernel(const float* __restrict__ q, const float* __restrict__ k,
                const float* __restrict__ v, const int* __restrict__ mask,
                float* __restrict__ out, int T, int H)
{
    extern __shared__ char smraw[];
    float*  sM = (float*)smraw;                       // 192 floats (pad to 256)
    __half* sK = (__half*)(smraw + 1024);             // 192 x 72
    __half* sV = sK + WROWS * KVSTR;                  // 192 x 72

    const int j   = blockIdx.x;          // pair of query blocks
    const int h   = blockIdx.y;
    const int b   = blockIdx.z;
    const int tid = threadIdx.x;         // 256 threads
    const int wp  = tid >> 5;            // 0..7
    const int wpl = wp & 3;              // warp within group
    const int roff = (wp >> 2) * WSZ;    // group row offset: 0 or 64
    const int ln  = tid & 31;
    const int g   = ln >> 2;             // 0..7
    const int t   = ln & 3;              // 0..3

    const long rowstride = (long)H * DIM;
    const long bbase     = (long)b * T * rowstride;
    const int  q0        = j * QBLK;

    // ---- Q loads FIRST (latency overlaps the KV fill below)
    const int ia = wpl * 16 + g;                      // local row within group's 64
    const int ib = ia + 8;
    const float* qra = q + bbase + (long)(q0 + roff + ia) * rowstride + h * DIM;
    const float* qrb = qra + 8 * rowstride;
    float4 qfa[4], qfb[4];
    #pragma unroll
    for (int ks = 0; ks < 4; ++ks) {
        qfa[ks] = __ldcs((const float4*)(qra + ks * 16 + 4 * t));
        qfb[ks] = __ldcs((const float4*)(qrb + ks * 16 + 4 * t));
    }

    // ---- mask window: rows [q0-64, q0+128)
    if (tid < WROWS) {
        int kg = q0 + tid - WSZ;
        sM[tid] = (kg >= 0) ? (float)mask[(long)b * T + kg] : 0.0f;
    }

    // ---- K, V fill (192 rows) as fp16 with column permutation
    #pragma unroll
    for (int it = 0; it < 12; ++it) {
        int idx = tid + it * 256;            // 192 rows * 16 float4
        int r   = idx >> 4;
        int c   = idx & 15;                  // source float4: actual cols 4c..4c+3
        int kg  = q0 + r - WSZ;
        float4 kv = make_float4(0.f, 0.f, 0.f, 0.f);
        float4 vv = make_float4(0.f, 0.f, 0.f, 0.f);
        if (kg >= 0) {
            long off = bbase + (long)kg * rowstride + h * DIM + c * 4;
            kv = *(const float4*)(k + off);
            vv = *(const float4*)(v + off);
        }
        const int pbase = r * KVSTR + ((c >> 2) << 4) + ((c & 3) << 1);
        *(uint32_t*)(sK + pbase)     = pack2h(kv.x, kv.y);
        *(uint32_t*)(sK + pbase + 8) = pack2h(kv.z, kv.w);
        *(uint32_t*)(sV + pbase)     = pack2h(vv.x, vv.y);
        *(uint32_t*)(sV + pbase + 8) = pack2h(vv.z, vv.w);
    }

    // ---- band masks (ALU-only; fills barrier wait): diff = 8x + 2t + u - g
    unsigned bnda = 0, bndb = 0;
    #pragma unroll
    for (int x = 0; x < 10; ++x) {
        #pragma unroll
        for (int u = 0; u < 2; ++u) {
            const int d = 8 * x + 2 * t + u - g;
            if (d >= 1 && d <= WSZ)          bnda |= 1u << (2 * x + u);
            if (d >= 9 && d <= WSZ + 8)      bndb |= 1u << (2 * x + u);
        }
    }

    // ---- pack Q fragments (K-permutation makes them contiguous)
    uint32_t aQ[4][4];
    #pragma unroll
    for (int ks = 0; ks < 4; ++ks) {
        aQ[ks][0] = pack2h(qfa[ks].x * QSCALE, qfa[ks].y * QSCALE);
        aQ[ks][2] = pack2h(qfa[ks].z * QSCALE, qfa[ks].w * QSCALE);
        aQ[ks][1] = pack2h(qfb[ks].x * QSCALE, qfb[ks].y * QSCALE);
        aQ[ks][3] = pack2h(qfb[ks].z * QSCALE, qfb[ks].w * QSCALE);
    }

    __syncthreads();

    const uint32_t sK_u = (uint32_t)__cvta_generic_to_shared(sK);
    const uint32_t sV_u = (uint32_t)__cvta_generic_to_shared(sV);

    const int r8   = ln & 7;
    const int hi8  = (ln >> 3) & 1;
    const int hi16 = ln >> 4;

    // ---- QK^T: band tiles x = 0..9 within this group's 128-row key window
    float S[10][4];
    #pragma unroll
    for (int x = 0; x < 10; ++x)
        S[x][0] = S[x][1] = S[x][2] = S[x][3] = 0.f;

    #pragma unroll
    for (int e = 0; e < 5; ++e) {
        const int key  = roff + (2 * wpl + 2 * e) * 8 + (hi16 << 3) + r8;
        const uint32_t rowaddr = sK_u + (uint32_t)(key * KVSTR) * 2;
        #pragma unroll
        for (int ks = 0; ks < 4; ++ks) {
            const int hoff = ks * 16 + (hi8 << 3);
            uint32_t b0, b1, b2, b3;
            ldsm_x4(b0, b1, b2, b3, rowaddr + (uint32_t)hoff * 2);
            mma_f16(S[2 * e],     aQ[ks][0], aQ[ks][1], aQ[ks][2], aQ[ks][3], b0, b1);
            mma_f16(S[2 * e + 1], aQ[ks][0], aQ[ks][1], aQ[ks][2], aQ[ks][3], b2, b3);
        }
    }

    // ---- unsafe softmax in exp2 domain; validity as multiply; split sums
    uint32_t P[10][2];
    float sa0 = 0.f, sa1 = 0.f, sb0 = 0.f, sb1 = 0.f;
    #pragma unroll
    for (int x = 0; x < 10; ++x) {
        const int mbase = roff + (2 * wpl + x) * 8 + 2 * t;
        const float2 mm = *(const float2*)(sM + mbase);
        const float va0 = ((bnda >> (2 * x))     & 1u) ? mm.x : 0.f;
        const float va1 = ((bnda >> (2 * x + 1)) & 1u) ? mm.y : 0.f;
        const float vb0 = ((bndb >> (2 * x))     & 1u) ? mm.x : 0.f;
        const float vb1 = ((bndb >> (2 * x + 1)) & 1u) ? mm.y : 0.f;
        const float pa0 = exp2f(S[x][0]) * va0;
        const float pa1 = exp2f(S[x][1]) * va1;
        const float pb0 = exp2f(S[x][2]) * vb0;
        const float pb1 = exp2f(S[x][3]) * vb1;
        sa0 += pa0;  sa1 += pa1;
        sb0 += pb0;  sb1 += pb1;
        P[x][0] = pack2h(pa0, pa1);
        P[x][1] = pack2h(pb0, pb1);
    }
    float sa = sa0 + sa1;
    float sb = sb0 + sb1;
    sa += __shfl_xor_sync(0xffffffffu, sa, 1);
    sa += __shfl_xor_sync(0xffffffffu, sa, 2);
    sb += __shfl_xor_sync(0xffffffffu, sb, 1);
    sb += __shfl_xor_sync(0xffffffffu, sb, 2);
    const float inva = (sa > 0.f) ? (1.f / sa) : 0.f;
    const float invb = (sb > 0.f) ? (1.f / sb) : 0.f;
    const __half2 h2a = __floats2half2_rn(inva, inva);
    const __half2 h2b = __floats2half2_rn(invb, invb);

    // ---- P @ V
    float O[8][4];
    #pragma unroll
    for (int nv = 0; nv < 8; ++nv)
        O[nv][0] = O[nv][1] = O[nv][2] = O[nv][3] = 0.f;

    #pragma unroll
    for (int s = 0; s < 5; ++s) {
        __half2 q0h = __hmul2(*(__half2*)&P[2 * s][0],     h2a);
        __half2 q1h = __hmul2(*(__half2*)&P[2 * s][1],     h2b);
        __half2 q2h = __hmul2(*(__half2*)&P[2 * s + 1][0], h2a);
        __half2 q3h = __hmul2(*(__half2*)&P[2 * s + 1][1], h2b);
        const uint32_t pa0 = *(uint32_t*)&q0h;
        const uint32_t pa1 = *(uint32_t*)&q1h;
        const uint32_t pa2 = *(uint32_t*)&q2h;
        const uint32_t pa3 = *(uint32_t*)&q3h;

        const int key = roff + (2 * wpl + 2 * s) * 8 + (hi8 << 3) + r8;
        const uint32_t rowaddr = sV_u + (uint32_t)(key * KVSTR) * 2;
        #pragma unroll
        for (int nd = 0; nd < 4; ++nd) {
            const int hoff = nd * 16 + (hi16 << 3);
            uint32_t b0, b1, b2, b3;
            ldsm_x4_t(b0, b1, b2, b3, rowaddr + (uint32_t)hoff * 2);
            mma_f16(O[2 * nd],     pa0, pa1, pa2, pa3, b0, b1);
            mma_f16(O[2 * nd + 1], pa0, pa1, pa2, pa3, b2, b3);
        }
    }

    // ---- epilogue: query-mask, float4 stores thanks to V permutation
    const float qma = sM[roff + WSZ + ia];
    const float qmb = sM[roff + WSZ + ib];
    const long oa = bbase + (long)(q0 + roff + ia) * rowstride + h * DIM;
    const long ob = bbase + (long)(q0 + roff + ib) * rowstride + h * DIM;
    #pragma unroll
    for (int m = 0; m < 4; ++m) {
        const int col = 16 * m + 4 * t;
        __stcs((float4*)(out + oa + col),
               make_float4(O[2 * m][0] * qma, O[2 * m][1] * qma,
                           O[2 * m + 1][0] * qma, O[2 * m + 1][1] * qma));
        __stcs((float4*)(out + ob + col),
               make_float4(O[2 * m][2] * qmb, O[2 * m][3] * qmb,
                           O[2 * m + 1][2] * qmb, O[2 * m + 1][3] * qmb));
    }
}

extern "C" void kernel_launch(void* const* d_in, const int* in_sizes, int n_in,
                              void* d_out, int out_size)
{
    const float* q    = (const float*)d_in[0];
    const float* k    = (const float*)d_in[1];
    const float* v    = (const float*)d_in[2];
    const int*   mask = (const int*)d_in[3];

    const int BT = in_sizes[3];            // b*t
    const int H  = in_sizes[0] / BT / DIM; // heads
    const int B  = 4;
    const int T  = BT / B;

    const int smem_bytes = 1024 + 2 * WROWS * KVSTR * (int)sizeof(__half);
    cudaFuncSetAttribute(lca_kernel, cudaFuncAttributeMaxDynamicSharedMemorySize, smem_bytes);

    dim3 grid(T / QBLK, H, B);
    lca_kernel<<<grid, 256, smem_bytes>>>(q, k, v, mask, (float*)d_out, T, H);
}